// round 6
// baseline (speedup 1.0000x reference)
#include <cuda_runtime.h>
#include <cuda_bf16.h>
#include <math.h>

// Fast path: D=512, K=128, balanced contiguous labels.
// One CTA (1024 threads, 32 warps) per class; each warp handles 4 rows with
// an online-softmax accumulator held in registers (16 floats/lane = 512/warp).
// Features are read from DRAM exactly once and never spilled.
#define D_MODEL 512
#define K_SHOT  128
#define TPB     1024
#define NWARPS  (TPB / 32)
#define ROWS_PER_WARP (K_SHOT / NWARPS)   // 4

// dynamic smem layout (floats): sem[512] | acc[32*512] | m[32] | z[32]
#define SM_SEM_O 0
#define SM_ACC_O (SM_SEM_O + D_MODEL)
#define SM_M_O   (SM_ACC_O + NWARPS * D_MODEL)
#define SM_Z_O   (SM_M_O + NWARPS)
#define SM_FLOATS (SM_Z_O + NWARPS)
#define SM_BYTES  (SM_FLOATS * sizeof(float))

__global__ __launch_bounds__(TPB, 1)
void proto_fast_kernel(const float* __restrict__ feats,
                       const float* __restrict__ sem,
                       float* __restrict__ out)
{
    extern __shared__ float sm[];
    float* s_sem = sm + SM_SEM_O;
    float* s_acc = sm + SM_ACC_O;
    float* s_m   = sm + SM_M_O;
    float* s_z   = sm + SM_Z_O;

    const int tid  = threadIdx.x;
    const int c    = blockIdx.x;
    const int wid  = tid >> 5;
    const int lane = tid & 31;

    // ---- semantics -> smem (coalesced float4) ----
    const float4* semg = (const float4*)(sem + (size_t)c * D_MODEL);
    if (tid < D_MODEL / 4) ((float4*)s_sem)[tid] = semg[tid];
    __syncthreads();

    // ---- semantics -> registers (lane owns float4 idx lane+32k, k=0..3) ----
    const float4* semv = (const float4*)s_sem;
    float4 sv0 = semv[lane];
    float4 sv1 = semv[lane + 32];
    float4 sv2 = semv[lane + 64];
    float4 sv3 = semv[lane + 96];

    // ---- sem norm (once per warp) ----
    float ps = sv0.x*sv0.x + sv0.y*sv0.y + sv0.z*sv0.z + sv0.w*sv0.w
             + sv1.x*sv1.x + sv1.y*sv1.y + sv1.z*sv1.z + sv1.w*sv1.w
             + sv2.x*sv2.x + sv2.y*sv2.y + sv2.z*sv2.z + sv2.w*sv2.w
             + sv3.x*sv3.x + sv3.y*sv3.y + sv3.z*sv3.z + sv3.w*sv3.w;
#pragma unroll
    for (int s = 16; s > 0; s >>= 1)
        ps += __shfl_xor_sync(0xFFFFFFFFu, ps, s);
    const float inv_sn = 1.f / fmaxf(sqrtf(ps), 1e-8f);

    // ---- online softmax over this warp's 4 rows ----
    float m = -INFINITY, Z = 0.f;
    float4 a0 = {0,0,0,0}, a1 = {0,0,0,0}, a2 = {0,0,0,0}, a3 = {0,0,0,0};

    const float4* fbase =
        (const float4*)(feats + ((size_t)c * K_SHOT + wid * ROWS_PER_WARP) * D_MODEL);

#pragma unroll
    for (int i = 0; i < ROWS_PER_WARP; i++) {
        const float4* fr = fbase + (size_t)i * (D_MODEL / 4);
        float4 x0 = fr[lane];
        float4 x1 = fr[lane + 32];
        float4 x2 = fr[lane + 64];
        float4 x3 = fr[lane + 96];

        float pd = x0.x*sv0.x + x0.y*sv0.y + x0.z*sv0.z + x0.w*sv0.w
                 + x1.x*sv1.x + x1.y*sv1.y + x1.z*sv1.z + x1.w*sv1.w
                 + x2.x*sv2.x + x2.y*sv2.y + x2.z*sv2.z + x2.w*sv2.w
                 + x3.x*sv3.x + x3.y*sv3.y + x3.z*sv3.z + x3.w*sv3.w;
        float pn = x0.x*x0.x + x0.y*x0.y + x0.z*x0.z + x0.w*x0.w
                 + x1.x*x1.x + x1.y*x1.y + x1.z*x1.z + x1.w*x1.w
                 + x2.x*x2.x + x2.y*x2.y + x2.z*x2.z + x2.w*x2.w
                 + x3.x*x3.x + x3.y*x3.y + x3.z*x3.z + x3.w*x3.w;
#pragma unroll
        for (int s = 16; s > 0; s >>= 1) {
            pd += __shfl_xor_sync(0xFFFFFFFFu, pd, s);
            pn += __shfl_xor_sync(0xFFFFFFFFu, pn, s);
        }
        const float sim = pd * inv_sn / fmaxf(sqrtf(pn), 1e-8f);

        const float mn    = fmaxf(m, sim);
        const float scale = __expf(m - mn);    // first iter: exp(-inf)=0
        const float e     = __expf(sim - mn);
        Z = Z * scale + e;
        m = mn;
        a0.x = a0.x*scale + e*x0.x;  a0.y = a0.y*scale + e*x0.y;
        a0.z = a0.z*scale + e*x0.z;  a0.w = a0.w*scale + e*x0.w;
        a1.x = a1.x*scale + e*x1.x;  a1.y = a1.y*scale + e*x1.y;
        a1.z = a1.z*scale + e*x1.z;  a1.w = a1.w*scale + e*x1.w;
        a2.x = a2.x*scale + e*x2.x;  a2.y = a2.y*scale + e*x2.y;
        a2.z = a2.z*scale + e*x2.z;  a2.w = a2.w*scale + e*x2.w;
        a3.x = a3.x*scale + e*x3.x;  a3.y = a3.y*scale + e*x3.y;
        a3.z = a3.z*scale + e*x3.z;  a3.w = a3.w*scale + e*x3.w;
    }

    // ---- dump warp partials ----
    float4* adst = (float4*)(s_acc + (size_t)wid * D_MODEL);
    adst[lane]      = a0;
    adst[lane + 32] = a1;
    adst[lane + 64] = a2;
    adst[lane + 96] = a3;
    if (lane == 0) { s_m[wid] = m; s_z[wid] = Z; }
    __syncthreads();

    // ---- warp 0: merge the 32 (m, Z) pairs -> per-warp coefficients ----
    if (tid < 32) {
        float mw = s_m[tid];
        float gm = mw;
#pragma unroll
        for (int s = 16; s > 0; s >>= 1)
            gm = fmaxf(gm, __shfl_xor_sync(0xFFFFFFFFu, gm, s));
        float cf = __expf(mw - gm);
        float zg = cf * s_z[tid];
#pragma unroll
        for (int s = 16; s > 0; s >>= 1)
            zg += __shfl_xor_sync(0xFFFFFFFFu, zg, s);
        s_m[tid] = cf / zg;   // final per-warp weight
    }
    __syncthreads();

    // ---- column-wise combine of 32 partials, coalesced store ----
    if (tid < D_MODEL) {
        float acc = 0.f;
#pragma unroll
        for (int w = 0; w < NWARPS; w++)
            acc += s_acc[(size_t)w * D_MODEL + tid] * s_m[w];
        out[(size_t)c * D_MODEL + tid] = acc;
    }
}

// Generic fallback (contiguous balanced labels, runtime K/D).
__global__ void proto_generic_kernel(const float* __restrict__ feats,
                                     const float* __restrict__ sem,
                                     float* __restrict__ out, int K, int D)
{
    extern __shared__ float s_simg[];  // K floats
    const int c    = blockIdx.x;
    const int wid  = threadIdx.x >> 5;
    const int lane = threadIdx.x & 31;
    const int nw   = blockDim.x >> 5;
    const float* S = sem + (size_t)c * D;

    for (int r = wid; r < K; r += nw) {
        const float* F = feats + ((size_t)c * K + r) * D;
        float pd = 0.f, pn = 0.f, ps = 0.f;
        for (int j = lane; j < D; j += 32) {
            float fv = F[j], sv = S[j];
            pd += fv * sv; pn += fv * fv; ps += sv * sv;
        }
        for (int s = 16; s > 0; s >>= 1) {
            pd += __shfl_xor_sync(0xFFFFFFFFu, pd, s);
            pn += __shfl_xor_sync(0xFFFFFFFFu, pn, s);
            ps += __shfl_xor_sync(0xFFFFFFFFu, ps, s);
        }
        if (lane == 0)
            s_simg[r] = pd / (fmaxf(sqrtf(pn), 1e-8f) * fmaxf(sqrtf(ps), 1e-8f));
    }
    __syncthreads();

    if (threadIdx.x == 0) {
        float m = -INFINITY;
        for (int r = 0; r < K; r++) m = fmaxf(m, s_simg[r]);
        float z = 0.f;
        for (int r = 0; r < K; r++) { float e = expf(s_simg[r] - m); s_simg[r] = e; z += e; }
        float inv = 1.f / z;
        for (int r = 0; r < K; r++) s_simg[r] *= inv;
    }
    __syncthreads();

    for (int j = threadIdx.x; j < D; j += blockDim.x) {
        float acc = 0.f;
        for (int r = 0; r < K; r++)
            acc += s_simg[r] * feats[((size_t)c * K + r) * D + j];
        out[(size_t)c * D + j] = acc;
    }
}

extern "C" void kernel_launch(void* const* d_in, const int* in_sizes, int n_in,
                              void* d_out, int out_size)
{
    const float* feats = (const float*)d_in[0];
    const float* sem   = (const float*)d_in[3];

    const int n_rows = in_sizes[1];
    const int D      = in_sizes[0] / n_rows;
    const int n_way  = in_sizes[3] / D;
    const int K      = n_rows / n_way;

    float* out = (float*)d_out;

    if (D == D_MODEL && K == K_SHOT) {
        cudaFuncSetAttribute(proto_fast_kernel,
                             cudaFuncAttributeMaxDynamicSharedMemorySize,
                             (int)SM_BYTES);
        proto_fast_kernel<<<n_way, TPB, SM_BYTES>>>(feats, sem, out);
    } else {
        proto_generic_kernel<<<n_way, 256, K * sizeof(float)>>>(feats, sem, out, K, D);
    }
}

// round 8
// speedup vs baseline: 1.2437x; 1.2437x over previous
#include <cuda_runtime.h>
#include <cuda_bf16.h>
#include <stdint.h>
#include <math.h>

// Fast path: D=512, K=128, balanced contiguous labels.
// One CTA (512 threads, 16 warps) per class. Feature rows are streamed into
// shared memory with a 4-stage cp.async pipeline (8 chunks x 16 rows x 2KB),
// decoupling DRAM latency from the per-row reduction chains. Each warp owns
// one row per chunk (8 rows total) with an online-softmax accumulator held
// in registers (16 floats/lane). Features are read from DRAM exactly once.
#define D_MODEL 512
#define K_SHOT  128
#define TPB     512
#define NWARPS  (TPB / 32)            // 16
#define CHUNK_ROWS 16
#define NCHUNK  (K_SHOT / CHUNK_ROWS) // 8
#define NSTAGE  4
#define CHUNK_F (CHUNK_ROWS * D_MODEL)   // 8192 floats = 32 KB
#define CHUNK_V4 (CHUNK_F / 4)           // 2048 float4

// dynamic smem (floats): stage[4][8192] | sem[512] | m[16] | z[16]
#define SM_STAGE_O 0
#define SM_SEM_O  (NSTAGE * CHUNK_F)
#define SM_M_O    (SM_SEM_O + D_MODEL)
#define SM_Z_O    (SM_M_O + NWARPS)
#define SM_FLOATS (SM_Z_O + NWARPS)
#define SM_BYTES  (SM_FLOATS * sizeof(float))

__device__ __forceinline__ void cp_async16(unsigned int saddr, const void* gptr) {
    asm volatile("cp.async.cg.shared.global [%0], [%1], 16;"
                 :: "r"(saddr), "l"(gptr));
}
#define CP_COMMIT() asm volatile("cp.async.commit_group;" ::: "memory")

__global__ __launch_bounds__(TPB, 1)
void proto_fast_kernel(const float* __restrict__ feats,
                       const float* __restrict__ sem,
                       float* __restrict__ out)
{
    extern __shared__ float sm[];
    float* s_stage = sm + SM_STAGE_O;
    float* s_sem   = sm + SM_SEM_O;
    float* s_m     = sm + SM_M_O;
    float* s_z     = sm + SM_Z_O;

    const int tid  = threadIdx.x;
    const int c    = blockIdx.x;
    const int wid  = tid >> 5;
    const int lane = tid & 31;

    const float4* fg = (const float4*)(feats + (size_t)c * K_SHOT * D_MODEL);
    const unsigned int stage_base =
        (unsigned int)__cvta_generic_to_shared((void*)s_stage);

    // ---- prologue: issue chunks 0..2 into stage bufs 0..2 ----
#pragma unroll
    for (int t = 0; t < NSTAGE - 1; t++) {
        unsigned int sbuf = stage_base + (unsigned int)(t * CHUNK_F * 4);
#pragma unroll
        for (int k = 0; k < 4; k++) {
            int p = tid + k * TPB;                      // float4 idx in chunk
            cp_async16(sbuf + (unsigned int)p * 16u,
                       (const void*)(fg + (size_t)t * CHUNK_V4 + p));
        }
        CP_COMMIT();
    }

    // ---- semantics -> smem -> registers ----
    const float4* semg = (const float4*)(sem + (size_t)c * D_MODEL);
    if (tid < D_MODEL / 4) ((float4*)s_sem)[tid] = semg[tid];
    __syncthreads();
    const float4* semv = (const float4*)s_sem;
    float4 sv0 = semv[lane];
    float4 sv1 = semv[lane + 32];
    float4 sv2 = semv[lane + 64];
    float4 sv3 = semv[lane + 96];

    float ps = sv0.x*sv0.x + sv0.y*sv0.y + sv0.z*sv0.z + sv0.w*sv0.w
             + sv1.x*sv1.x + sv1.y*sv1.y + sv1.z*sv1.z + sv1.w*sv1.w
             + sv2.x*sv2.x + sv2.y*sv2.y + sv2.z*sv2.z + sv2.w*sv2.w
             + sv3.x*sv3.x + sv3.y*sv3.y + sv3.z*sv3.z + sv3.w*sv3.w;
#pragma unroll
    for (int s = 16; s > 0; s >>= 1)
        ps += __shfl_xor_sync(0xFFFFFFFFu, ps, s);
    const float inv_sn = 1.f / fmaxf(sqrtf(ps), 1e-8f);

    // ---- online softmax over this warp's 8 rows (one per chunk) ----
    float m = -INFINITY, Z = 0.f;
    float4 a0 = {0,0,0,0}, a1 = {0,0,0,0}, a2 = {0,0,0,0}, a3 = {0,0,0,0};

#pragma unroll
    for (int s = 0; s < NCHUNK; s++) {
        // wait for chunk s; keep up to 2 later groups in flight
        if (NCHUNK - 1 - s >= 2)
            asm volatile("cp.async.wait_group 2;" ::: "memory");
        else if (NCHUNK - 1 - s == 1)
            asm volatile("cp.async.wait_group 1;" ::: "memory");
        else
            asm volatile("cp.async.wait_group 0;" ::: "memory");
        __syncthreads();

        // refill: issue chunk s+3 into buf (s+3)%4 (its old chunk consumed)
        if (s + NSTAGE - 1 < NCHUNK) {
            const int t = s + NSTAGE - 1;
            unsigned int sbuf =
                stage_base + (unsigned int)((t % NSTAGE) * CHUNK_F * 4);
#pragma unroll
            for (int k = 0; k < 4; k++) {
                int p = tid + k * TPB;
                cp_async16(sbuf + (unsigned int)p * 16u,
                           (const void*)(fg + (size_t)t * CHUNK_V4 + p));
            }
            CP_COMMIT();
        }

        // compute: warp wid owns row wid of chunk s
        const float4* rowv =
            (const float4*)(s_stage + (size_t)(s % NSTAGE) * CHUNK_F
                            + (size_t)wid * D_MODEL);
        float4 x0 = rowv[lane];
        float4 x1 = rowv[lane + 32];
        float4 x2 = rowv[lane + 64];
        float4 x3 = rowv[lane + 96];

        float pd = x0.x*sv0.x + x0.y*sv0.y + x0.z*sv0.z + x0.w*sv0.w
                 + x1.x*sv1.x + x1.y*sv1.y + x1.z*sv1.z + x1.w*sv1.w
                 + x2.x*sv2.x + x2.y*sv2.y + x2.z*sv2.z + x2.w*sv2.w
                 + x3.x*sv3.x + x3.y*sv3.y + x3.z*sv3.z + x3.w*sv3.w;
        float pn = x0.x*x0.x + x0.y*x0.y + x0.z*x0.z + x0.w*x0.w
                 + x1.x*x1.x + x1.y*x1.y + x1.z*x1.z + x1.w*x1.w
                 + x2.x*x2.x + x2.y*x2.y + x2.z*x2.z + x2.w*x2.w
                 + x3.x*x3.x + x3.y*x3.y + x3.z*x3.z + x3.w*x3.w;
#pragma unroll
        for (int sh = 16; sh > 0; sh >>= 1) {
            pd += __shfl_xor_sync(0xFFFFFFFFu, pd, sh);
            pn += __shfl_xor_sync(0xFFFFFFFFu, pn, sh);
        }
        const float sim = pd * inv_sn / fmaxf(sqrtf(pn), 1e-8f);

        const float mn    = fmaxf(m, sim);
        const float scale = __expf(m - mn);   // first iter: exp(-inf)=0
        const float e     = __expf(sim - mn);
        Z = Z * scale + e;
        m = mn;
        a0.x = a0.x*scale + e*x0.x;  a0.y = a0.y*scale + e*x0.y;
        a0.z = a0.z*scale + e*x0.z;  a0.w = a0.w*scale + e*x0.w;
        a1.x = a1.x*scale + e*x1.x;  a1.y = a1.y*scale + e*x1.y;
        a1.z = a1.z*scale + e*x1.z;  a1.w = a1.w*scale + e*x1.w;
        a2.x = a2.x*scale + e*x2.x;  a2.y = a2.y*scale + e*x2.y;
        a2.z = a2.z*scale + e*x2.z;  a2.w = a2.w*scale + e*x2.w;
        a3.x = a3.x*scale + e*x3.x;  a3.y = a3.y*scale + e*x3.y;
        a3.z = a3.z*scale + e*x3.z;  a3.w = a3.w*scale + e*x3.w;
    }

    // ---- dump warp partials (reuse stage buf 0; all consumers are done) ----
    __syncthreads();
    float4* adst = (float4*)(s_stage + (size_t)wid * D_MODEL);
    adst[lane]      = a0;
    adst[lane + 32] = a1;
    adst[lane + 64] = a2;
    adst[lane + 96] = a3;
    if (lane == 0) { s_m[wid] = m; s_z[wid] = Z; }
    __syncthreads();

    // ---- warp 0: merge 16 (m, Z) pairs -> per-warp weights ----
    if (tid < 32) {
        float mw = (tid < NWARPS) ? s_m[tid] : -INFINITY;
        float zw = (tid < NWARPS) ? s_z[tid] : 0.f;
        float gm = mw;
#pragma unroll
        for (int s = 16; s > 0; s >>= 1)
            gm = fmaxf(gm, __shfl_xor_sync(0xFFFFFFFFu, gm, s));
        float cf = __expf(mw - gm);
        float zg = cf * zw;
#pragma unroll
        for (int s = 16; s > 0; s >>= 1)
            zg += __shfl_xor_sync(0xFFFFFFFFu, zg, s);
        if (tid < NWARPS) s_m[tid] = cf / zg;
    }
    __syncthreads();

    // ---- column combine of 16 partials, coalesced store ----
    {
        float acc = 0.f;
#pragma unroll
        for (int w = 0; w < NWARPS; w++)
            acc += s_stage[(size_t)w * D_MODEL + tid] * s_m[w];
        out[(size_t)c * D_MODEL + tid] = acc;
    }
}

// Generic fallback (contiguous balanced labels, runtime K/D).
__global__ void proto_generic_kernel(const float* __restrict__ feats,
                                     const float* __restrict__ sem,
                                     float* __restrict__ out, int K, int D)
{
    extern __shared__ float s_simg[];  // K floats
    const int c    = blockIdx.x;
    const int wid  = threadIdx.x >> 5;
    const int lane = threadIdx.x & 31;
    const int nw   = blockDim.x >> 5;
    const float* S = sem + (size_t)c * D;

    for (int r = wid; r < K; r += nw) {
        const float* F = feats + ((size_t)c * K + r) * D;
        float pd = 0.f, pn = 0.f, ps = 0.f;
        for (int j = lane; j < D; j += 32) {
            float fv = F[j], sv = S[j];
            pd += fv * sv; pn += fv * fv; ps += sv * sv;
        }
        for (int s = 16; s > 0; s >>= 1) {
            pd += __shfl_xor_sync(0xFFFFFFFFu, pd, s);
            pn += __shfl_xor_sync(0xFFFFFFFFu, pn, s);
            ps += __shfl_xor_sync(0xFFFFFFFFu, ps, s);
        }
        if (lane == 0)
            s_simg[r] = pd / (fmaxf(sqrtf(pn), 1e-8f) * fmaxf(sqrtf(ps), 1e-8f));
    }
    __syncthreads();

    if (threadIdx.x == 0) {
        float m = -INFINITY;
        for (int r = 0; r < K; r++) m = fmaxf(m, s_simg[r]);
        float z = 0.f;
        for (int r = 0; r < K; r++) { float e = expf(s_simg[r] - m); s_simg[r] = e; z += e; }
        float inv = 1.f / z;
        for (int r = 0; r < K; r++) s_simg[r] *= inv;
    }
    __syncthreads();

    for (int j = threadIdx.x; j < D; j += blockDim.x) {
        float acc = 0.f;
        for (int r = 0; r < K; r++)
            acc += s_simg[r] * feats[((size_t)c * K + r) * D + j];
        out[(size_t)c * D + j] = acc;
    }
}

extern "C" void kernel_launch(void* const* d_in, const int* in_sizes, int n_in,
                              void* d_out, int out_size)
{
    const float* feats = (const float*)d_in[0];
    const float* sem   = (const float*)d_in[3];

    const int n_rows = in_sizes[1];
    const int D      = in_sizes[0] / n_rows;
    const int n_way  = in_sizes[3] / D;
    const int K      = n_rows / n_way;

    float* out = (float*)d_out;

    if (D == D_MODEL && K == K_SHOT) {
        cudaFuncSetAttribute(proto_fast_kernel,
                             cudaFuncAttributeMaxDynamicSharedMemorySize,
                             (int)SM_BYTES);
        proto_fast_kernel<<<n_way, TPB, SM_BYTES>>>(feats, sem, out);
    } else {
        proto_generic_kernel<<<n_way, 256, K * sizeof(float)>>>(feats, sem, out, K, D);
    }
}

// round 9
// speedup vs baseline: 1.3525x; 1.0875x over previous
#include <cuda_runtime.h>
#include <cuda_bf16.h>
#include <stdint.h>
#include <math.h>

// Fast path: D=512, K=128, balanced contiguous labels.
// One CTA (256 threads, 8 warps) per class, 2 CTAs resident per SM.
// Each warp owns 16 contiguous rows and streams them through a warp-private
// 4-slot cp.async ring buffer (2KB/slot). No block-wide barriers in the main
// loop: each warp self-clocks on its own cp.async groups, and each lane only
// reads the smem bytes it loaded itself. Online softmax keeps the weighted
// accumulator in registers; features are read from DRAM exactly once.
#define D_MODEL 512
#define K_SHOT  128
#define TPB     256
#define NWARPS  (TPB / 32)          // 8
#define ROWS_PW (K_SHOT / NWARPS)   // 16 rows per warp
#define NSLOT   4
#define ROW_F   D_MODEL             // floats per row
#define SLOT_BYTES (ROW_F * 4)      // 2048 B

// dynamic smem (floats): stage[8][4][512] | sem[512] | m[8] | z[8]
#define SM_STAGE_O 0
#define SM_STAGE_F (NWARPS * NSLOT * ROW_F)   // 16384 floats = 64 KB
#define SM_SEM_O  (SM_STAGE_O + SM_STAGE_F)
#define SM_M_O    (SM_SEM_O + D_MODEL)
#define SM_Z_O    (SM_M_O + NWARPS)
#define SM_FLOATS (SM_Z_O + NWARPS)
#define SM_BYTES  (SM_FLOATS * sizeof(float))

__device__ __forceinline__ void cp_async16(unsigned int saddr, const void* gptr) {
    asm volatile("cp.async.cg.shared.global [%0], [%1], 16;"
                 :: "r"(saddr), "l"(gptr));
}
#define CP_COMMIT() asm volatile("cp.async.commit_group;" ::: "memory")
#define CP_WAIT(n)  asm volatile("cp.async.wait_group %0;" :: "n"(n) : "memory")

__global__ __launch_bounds__(TPB, 2)
void proto_fast_kernel(const float* __restrict__ feats,
                       const float* __restrict__ sem,
                       float* __restrict__ out)
{
    extern __shared__ float sm[];
    float* s_stage = sm + SM_STAGE_O;
    float* s_sem   = sm + SM_SEM_O;
    float* s_m     = sm + SM_M_O;
    float* s_z     = sm + SM_Z_O;

    const int tid  = threadIdx.x;
    const int c    = blockIdx.x;
    const int wid  = tid >> 5;
    const int lane = tid & 31;

    // this warp's 16 contiguous rows and private ring buffer
    const float4* fwarp =
        (const float4*)(feats + ((size_t)c * K_SHOT + (size_t)wid * ROWS_PW) * D_MODEL);
    float* my_stage = s_stage + (size_t)wid * NSLOT * ROW_F;
    const unsigned int ring_base =
        (unsigned int)__cvta_generic_to_shared((void*)my_stage);

    // ---- prologue: issue rows 0..2 into slots 0..2 (warp-local groups) ----
#pragma unroll
    for (int t = 0; t < NSLOT - 1; t++) {
        unsigned int sbuf = ring_base + (unsigned int)(t * SLOT_BYTES);
#pragma unroll
        for (int k = 0; k < 4; k++) {
            int p = lane + 32 * k;                  // float4 idx in row
            cp_async16(sbuf + (unsigned int)p * 16u,
                       (const void*)(fwarp + (size_t)t * (ROW_F / 4) + p));
        }
        CP_COMMIT();
    }

    // ---- semantics -> smem -> registers ----
    const float4* semg = (const float4*)(sem + (size_t)c * D_MODEL);
    if (tid < D_MODEL / 4) ((float4*)s_sem)[tid] = semg[tid];
    __syncthreads();
    const float4* semv = (const float4*)s_sem;
    float4 sv0 = semv[lane];
    float4 sv1 = semv[lane + 32];
    float4 sv2 = semv[lane + 64];
    float4 sv3 = semv[lane + 96];

    float ps = sv0.x*sv0.x + sv0.y*sv0.y + sv0.z*sv0.z + sv0.w*sv0.w
             + sv1.x*sv1.x + sv1.y*sv1.y + sv1.z*sv1.z + sv1.w*sv1.w
             + sv2.x*sv2.x + sv2.y*sv2.y + sv2.z*sv2.z + sv2.w*sv2.w
             + sv3.x*sv3.x + sv3.y*sv3.y + sv3.z*sv3.z + sv3.w*sv3.w;
#pragma unroll
    for (int s = 16; s > 0; s >>= 1)
        ps += __shfl_xor_sync(0xFFFFFFFFu, ps, s);
    const float inv_sn = 1.f / fmaxf(sqrtf(ps), 1e-8f);

    // ---- online softmax over this warp's 16 rows, warp-local pipeline ----
    float m = -INFINITY, Z = 0.f;
    float4 a0 = {0,0,0,0}, a1 = {0,0,0,0}, a2 = {0,0,0,0}, a3 = {0,0,0,0};

#pragma unroll
    for (int i = 0; i < ROWS_PW; i++) {
        // groups issued so far cover rows 0..min(i+2, 15); to guarantee row i
        // is complete, wait until <= (min(i+2,15) - i) groups remain pending.
        if (i + 2 <= ROWS_PW - 1)      CP_WAIT(2);
        else if (i + 1 <= ROWS_PW - 1) CP_WAIT(1);
        else                           CP_WAIT(0);

        const float4* rowv = (const float4*)(my_stage + (size_t)(i % NSLOT) * ROW_F);
        float4 x0 = rowv[lane];
        float4 x1 = rowv[lane + 32];
        float4 x2 = rowv[lane + 64];
        float4 x3 = rowv[lane + 96];

        // refill: issue row i+3 into slot (i+3)%4 (its previous row consumed)
        if (i + NSLOT - 1 < ROWS_PW) {
            const int t = i + NSLOT - 1;
            unsigned int sbuf =
                ring_base + (unsigned int)((t % NSLOT) * SLOT_BYTES);
#pragma unroll
            for (int k = 0; k < 4; k++) {
                int p = lane + 32 * k;
                cp_async16(sbuf + (unsigned int)p * 16u,
                           (const void*)(fwarp + (size_t)t * (ROW_F / 4) + p));
            }
            CP_COMMIT();
        }

        float pd = x0.x*sv0.x + x0.y*sv0.y + x0.z*sv0.z + x0.w*sv0.w
                 + x1.x*sv1.x + x1.y*sv1.y + x1.z*sv1.z + x1.w*sv1.w
                 + x2.x*sv2.x + x2.y*sv2.y + x2.z*sv2.z + x2.w*sv2.w
                 + x3.x*sv3.x + x3.y*sv3.y + x3.z*sv3.z + x3.w*sv3.w;
        float pn = x0.x*x0.x + x0.y*x0.y + x0.z*x0.z + x0.w*x0.w
                 + x1.x*x1.x + x1.y*x1.y + x1.z*x1.z + x1.w*x1.w
                 + x2.x*x2.x + x2.y*x2.y + x2.z*x2.z + x2.w*x2.w
                 + x3.x*x3.x + x3.y*x3.y + x3.z*x3.z + x3.w*x3.w;
#pragma unroll
        for (int sh = 16; sh > 0; sh >>= 1) {
            pd += __shfl_xor_sync(0xFFFFFFFFu, pd, sh);
            pn += __shfl_xor_sync(0xFFFFFFFFu, pn, sh);
        }
        const float sim = pd * inv_sn / fmaxf(sqrtf(pn), 1e-8f);

        const float mn    = fmaxf(m, sim);
        const float scale = __expf(m - mn);   // first iter: exp(-inf)=0
        const float e     = __expf(sim - mn);
        Z = Z * scale + e;
        m = mn;
        a0.x = a0.x*scale + e*x0.x;  a0.y = a0.y*scale + e*x0.y;
        a0.z = a0.z*scale + e*x0.z;  a0.w = a0.w*scale + e*x0.w;
        a1.x = a1.x*scale + e*x1.x;  a1.y = a1.y*scale + e*x1.y;
        a1.z = a1.z*scale + e*x1.z;  a1.w = a1.w*scale + e*x1.w;
        a2.x = a2.x*scale + e*x2.x;  a2.y = a2.y*scale + e*x2.y;
        a2.z = a2.z*scale + e*x2.z;  a2.w = a2.w*scale + e*x2.w;
        a3.x = a3.x*scale + e*x3.x;  a3.y = a3.y*scale + e*x3.y;
        a3.z = a3.z*scale + e*x3.z;  a3.w = a3.w*scale + e*x3.w;
    }

    // ---- dump warp partials into own ring region (slot 0) ----
    __syncthreads();   // all warps done consuming their rings
    float4* adst = (float4*)my_stage;
    adst[lane]      = a0;
    adst[lane + 32] = a1;
    adst[lane + 64] = a2;
    adst[lane + 96] = a3;
    if (lane == 0) { s_m[wid] = m; s_z[wid] = Z; }
    __syncthreads();

    // ---- warp 0: merge 8 (m, Z) pairs -> per-warp weights ----
    if (tid < 32) {
        float mw = (tid < NWARPS) ? s_m[tid] : -INFINITY;
        float zw = (tid < NWARPS) ? s_z[tid] : 0.f;
        float gm = mw;
#pragma unroll
        for (int s = 16; s > 0; s >>= 1)
            gm = fmaxf(gm, __shfl_xor_sync(0xFFFFFFFFu, gm, s));
        float cf = __expf(mw - gm);
        float zg = cf * zw;
#pragma unroll
        for (int s = 16; s > 0; s >>= 1)
            zg += __shfl_xor_sync(0xFFFFFFFFu, zg, s);
        if (tid < NWARPS) s_m[tid] = cf / zg;
    }
    __syncthreads();

    // ---- column combine of 8 partials; each thread does 2 columns ----
#pragma unroll
    for (int h = 0; h < 2; h++) {
        const int col = tid + h * TPB;
        float acc = 0.f;
#pragma unroll
        for (int w = 0; w < NWARPS; w++)
            acc += s_stage[(size_t)w * NSLOT * ROW_F + col] * s_m[w];
        out[(size_t)c * D_MODEL + col] = acc;
    }
}

// Generic fallback (contiguous balanced labels, runtime K/D).
__global__ void proto_generic_kernel(const float* __restrict__ feats,
                                     const float* __restrict__ sem,
                                     float* __restrict__ out, int K, int D)
{
    extern __shared__ float s_simg[];  // K floats
    const int c    = blockIdx.x;
    const int wid  = threadIdx.x >> 5;
    const int lane = threadIdx.x & 31;
    const int nw   = blockDim.x >> 5;
    const float* S = sem + (size_t)c * D;

    for (int r = wid; r < K; r += nw) {
        const float* F = feats + ((size_t)c * K + r) * D;
        float pd = 0.f, pn = 0.f, ps = 0.f;
        for (int j = lane; j < D; j += 32) {
            float fv = F[j], sv = S[j];
            pd += fv * sv; pn += fv * fv; ps += sv * sv;
        }
        for (int s = 16; s > 0; s >>= 1) {
            pd += __shfl_xor_sync(0xFFFFFFFFu, pd, s);
            pn += __shfl_xor_sync(0xFFFFFFFFu, pn, s);
            ps += __shfl_xor_sync(0xFFFFFFFFu, ps, s);
        }
        if (lane == 0)
            s_simg[r] = pd / (fmaxf(sqrtf(pn), 1e-8f) * fmaxf(sqrtf(ps), 1e-8f));
    }
    __syncthreads();

    if (threadIdx.x == 0) {
        float m = -INFINITY;
        for (int r = 0; r < K; r++) m = fmaxf(m, s_simg[r]);
        float z = 0.f;
        for (int r = 0; r < K; r++) { float e = expf(s_simg[r] - m); s_simg[r] = e; z += e; }
        float inv = 1.f / z;
        for (int r = 0; r < K; r++) s_simg[r] *= inv;
    }
    __syncthreads();

    for (int j = threadIdx.x; j < D; j += blockDim.x) {
        float acc = 0.f;
        for (int r = 0; r < K; r++)
            acc += s_simg[r] * feats[((size_t)c * K + r) * D + j];
        out[(size_t)c * D + j] = acc;
    }
}

extern "C" void kernel_launch(void* const* d_in, const int* in_sizes, int n_in,
                              void* d_out, int out_size)
{
    const float* feats = (const float*)d_in[0];
    const float* sem   = (const float*)d_in[3];

    const int n_rows = in_sizes[1];
    const int D      = in_sizes[0] / n_rows;
    const int n_way  = in_sizes[3] / D;
    const int K      = n_rows / n_way;

    float* out = (float*)d_out;

    if (D == D_MODEL && K == K_SHOT) {
        cudaFuncSetAttribute(proto_fast_kernel,
                             cudaFuncAttributeMaxDynamicSharedMemorySize,
                             (int)SM_BYTES);
        proto_fast_kernel<<<n_way, TPB, SM_BYTES>>>(feats, sem, out);
    } else {
        proto_generic_kernel<<<n_way, 256, K * sizeof(float)>>>(feats, sem, out, K, D);
    }
}